// round 12
// baseline (speedup 1.0000x reference)
#include <cuda_runtime.h>
#include <cuda_bf16.h>
#include <cstdint>
#include <cstring>

#define L1N 1024
#define DN  512
#define G4  2048

__device__ float d_buf0[1024 * 1024];
__device__ float d_buf1[1024 * 1024];
__device__ float d_A[2 * 1024 * 2048];
__device__ float d_mu[1024 * 512];
__device__ float d_ps[1024 * 512];
__device__ float d_z[1024 * 512];
__device__ float d_pos[1024];
__device__ float d_neg[1024];
__device__ float d_negf[1024];
__device__ double d_kl[1];
__device__ double d_sumy[1];

__device__ __nv_bfloat16 b_Wb[2 * 2048 * 1024];
__device__ __nv_bfloat16 b_Xb[1024 * 1024];
__device__ __nv_bfloat16 b_Gen[8192 * 512];
__device__ __nv_bfloat16 b_Gfrn[8192 * 512];
__device__ __nv_bfloat16 b_Gfr[1024 * 512];
__device__ __nv_bfloat16 b_zb[1024 * 512];
__device__ __nv_bfloat16 b_hb[1024 * 512];
__device__ __nv_bfloat16 b_t1[1024 * 512];
__device__ __nv_bfloat16 b_t2[1024 * 512];
__device__ __nv_bfloat16 b_Wm[4 * 512 * 512];

__device__ __forceinline__ float tanh_t(float x) {
    float r;
    asm("tanh.approx.f32 %0, %1;" : "=f"(r) : "f"(x));
    return r;
}
__device__ __forceinline__ float sigm_t(float x) {
    return fmaf(tanh_t(0.5f * x), 0.5f, 0.5f);
}
__device__ __forceinline__ uint32_t smem_u32(const void* p) {
    uint32_t a;
    asm("{ .reg .u64 t; cvta.to.shared.u64 t, %1; cvt.u32.u64 %0, t; }" : "=r"(a) : "l"(p));
    return a;
}
__device__ __forceinline__ __nv_bfloat162 as_bf2(uint32_t v) {
    __nv_bfloat162 r; memcpy(&r, &v, 4); return r;
}
__device__ __forceinline__ uint32_t as_u32(__nv_bfloat162 v) {
    uint32_t r; memcpy(&r, &v, 4); return r;
}
__device__ __forceinline__ uint32_t packbf(float a, float b) {
    __nv_bfloat162 t = __float22bfloat162_rn(make_float2(a, b));
    uint32_t v; memcpy(&v, &t, 4); return v;
}
__device__ __forceinline__ void bar_wait_cl(uint32_t addr, uint32_t par) {
    uint32_t done;
    do {
        asm volatile("{\n\t.reg .pred p;\n\t"
            "mbarrier.try_wait.parity.acquire.cluster.shared::cta.b64 p, [%1], %2, 0x989680;\n\t"
            "selp.b32 %0, 1, 0, p;\n\t}"
            : "=r"(done) : "r"(addr), "r"(par) : "memory");
    } while (!done);
}
__device__ __forceinline__ void arrive_peer(uint32_t addr, uint32_t rank) {
    asm volatile("{\n\t.reg .b32 ra;\n\t"
        "mapa.shared::cluster.u32 ra, %0, %1;\n\t"
        "mbarrier.arrive.release.cluster.shared::cluster.b64 _, [ra];\n\t}"
        :: "r"(addr), "r"(rank) : "memory");
}
__device__ __forceinline__ void st_peer_v2(uint32_t addr, uint32_t peer, uint32_t a, uint32_t b) {
    asm volatile("{\n\t.reg .b32 ra;\n\t"
        "mapa.shared::cluster.u32 ra, %0, %1;\n\t"
        "st.shared::cluster.v2.u32 [ra], {%2,%3};\n\t}"
        :: "r"(addr), "r"(peer), "r"(a), "r"(b) : "memory");
}
__device__ __forceinline__ void ldsm_x4(uint32_t& r0, uint32_t& r1, uint32_t& r2, uint32_t& r3, uint32_t addr) {
    asm volatile("ldmatrix.sync.aligned.m8n8.x4.shared.b16 {%0,%1,%2,%3}, [%4];"
        : "=r"(r0), "=r"(r1), "=r"(r2), "=r"(r3) : "r"(addr));
}
__device__ __forceinline__ void ldsm_x2(uint32_t& r0, uint32_t& r1, uint32_t addr) {
    asm volatile("ldmatrix.sync.aligned.m8n8.x2.shared.b16 {%0,%1}, [%2];"
        : "=r"(r0), "=r"(r1) : "r"(addr));
}
__device__ __forceinline__ void mma16816(float* d, const uint32_t* a, const uint32_t* b) {
    asm volatile("mma.sync.aligned.m16n8k16.row.col.f32.bf16.bf16.f32 "
        "{%0,%1,%2,%3}, {%4,%5,%6,%7}, {%8,%9}, {%0,%1,%2,%3};"
        : "+f"(d[0]), "+f"(d[1]), "+f"(d[2]), "+f"(d[3])
        : "r"(a[0]), "r"(a[1]), "r"(a[2]), "r"(a[3]), "r"(b[0]), "r"(b[1]));
}

__global__ void reset_kernel() {
    int i = blockIdx.x * 256 + threadIdx.x;
    if (i < 1024) { d_neg[i] = 0.f; d_negf[i] = 0.f; }
    if (i == 0) { d_kl[0] = 0.0; d_sumy[0] = 0.0; }
}

__global__ void gatherb_kernel(const float* __restrict__ E, const int* __restrict__ idx,
                               __nv_bfloat16* __restrict__ dst) {
    int r = blockIdx.x, t = threadIdx.x;  // 128 threads
    float4 v = *(const float4*)(E + (size_t)idx[r] * 512 + t * 4);
    ((uint2*)(dst + (size_t)r * 512))[t] = make_uint2(packbf(v.x, v.y), packbf(v.z, v.w));
}

__global__ void convb_kernel(const float* __restrict__ src, __nv_bfloat16* __restrict__ dst, int n4) {
    int i = blockIdx.x * 256 + threadIdx.x;
    if (i < n4) {
        float4 v = ((const float4*)src)[i];
        ((uint2*)dst)[i] = make_uint2(packbf(v.x, v.y), packbf(v.z, v.w));
    }
}

__global__ void hsum_kernel(__nv_bfloat16* __restrict__ hb) {
    int i = blockIdx.x * 256 + threadIdx.x;  // 524288
    int t = i >> 9, d = i & 511;
    hb[i] = __float2bfloat16(d_buf1[t * 1024 + d] + d_buf1[t * 1024 + 512 + d]);
}

// bf16 tensor-core GEMM: C[M][N] = A[M][K] @ B[N][K]^T (fp32 accum)
__global__ __launch_bounds__(256) void gemm_bf16_kernel(
    const __nv_bfloat16* __restrict__ A, int lda,
    const __nv_bfloat16* __restrict__ B, int ldb,
    const float* __restrict__ bias,
    float* __restrict__ C, __nv_bfloat16* __restrict__ Cb, int ldc,
    int K, int mode,
    const float* __restrict__ negf,
    float* __restrict__ rowsum,
    double* __restrict__ outsum)
{
    __shared__ __align__(16) __nv_bfloat16 As[64][40];
    __shared__ __align__(16) __nv_bfloat16 Bs[64][40];
    __shared__ float red[256];

    int tid = threadIdx.x;
    int wid = tid >> 5, lane = tid & 31;
    int m0 = blockIdx.y * 64, n0 = blockIdx.x * 64;
    int wm = (wid & 1) * 32, wn = (wid >> 1) * 16;
    int lr = tid >> 2, ls = (tid & 3) * 8;

    float acc[2][2][4] = {};

    uint32_t a_addr[2], b_addr[2];
    #pragma unroll
    for (int i = 0; i < 2; ++i)
        a_addr[i] = smem_u32(&As[wm + i * 16 + (lane & 15)][(lane >> 4) * 8]);
    #pragma unroll
    for (int j = 0; j < 2; ++j)
        b_addr[j] = smem_u32(&Bs[wn + j * 8 + (lane & 7)][((lane >> 3) & 1) * 8]);

    for (int k0 = 0; k0 < K; k0 += 32) {
        *(uint4*)&As[lr][ls] = *(const uint4*)(A + (size_t)(m0 + lr) * lda + k0 + ls);
        *(uint4*)&Bs[lr][ls] = *(const uint4*)(B + (size_t)(n0 + lr) * ldb + k0 + ls);
        __syncthreads();
        #pragma unroll
        for (int kk = 0; kk < 2; ++kk) {
            uint32_t af[2][4], bf[2][2];
            #pragma unroll
            for (int i = 0; i < 2; ++i)
                ldsm_x4(af[i][0], af[i][1], af[i][2], af[i][3], a_addr[i] + kk * 32);
            #pragma unroll
            for (int j = 0; j < 2; ++j)
                ldsm_x2(bf[j][0], bf[j][1], b_addr[j] + kk * 32);
            #pragma unroll
            for (int i = 0; i < 2; ++i)
                #pragma unroll
                for (int j = 0; j < 2; ++j)
                    mma16816(acc[i][j], af[i], bf[j]);
        }
        __syncthreads();
    }

    int qr = lane >> 2, qc = (lane & 3) * 2;
    if (mode <= 1) {
        #pragma unroll
        for (int i = 0; i < 2; ++i)
            #pragma unroll
            for (int r = 0; r < 2; ++r) {
                int row = m0 + wm + i * 16 + r * 8 + qr;
                #pragma unroll
                for (int j = 0; j < 2; ++j) {
                    int col = n0 + wn + j * 8 + qc;
                    float v0 = acc[i][j][r * 2 + 0] + (bias ? bias[col] : 0.f);
                    float v1 = acc[i][j][r * 2 + 1] + (bias ? bias[col + 1] : 0.f);
                    if (mode == 1) { v0 = fmaxf(v0, 0.f); v1 = fmaxf(v1, 0.f); }
                    if (C) *(float2*)(C + (size_t)row * ldc + col) = make_float2(v0, v1);
                    if (Cb) *(uint32_t*)(Cb + (size_t)row * ldc + col) = packbf(v0, v1);
                }
            }
    } else if (mode == 2) {
        #pragma unroll
        for (int i = 0; i < 2; ++i)
            #pragma unroll
            for (int r = 0; r < 2; ++r) {
                float s = 0.f;
                #pragma unroll
                for (int j = 0; j < 2; ++j)
                    s += __expf(acc[i][j][r * 2]) + __expf(acc[i][j][r * 2 + 1]);
                s += __shfl_xor_sync(0xffffffffu, s, 1);
                s += __shfl_xor_sync(0xffffffffu, s, 2);
                if ((lane & 3) == 0)
                    atomicAdd(rowsum + m0 + wm + i * 16 + r * 8 + qr, s);
            }
    } else {
        float ssum = 0.f;
        #pragma unroll
        for (int i = 0; i < 2; ++i)
            #pragma unroll
            for (int r = 0; r < 2; ++r) {
                float nf = negf[m0 + wm + i * 16 + r * 8 + qr];
                #pragma unroll
                for (int j = 0; j < 2; ++j) {
                    float e0 = __expf(acc[i][j][r * 2]);
                    float e1 = __expf(acc[i][j][r * 2 + 1]);
                    ssum += e0 / (e0 + nf) + e1 / (e1 + nf);
                }
            }
        red[tid] = ssum;
        __syncthreads();
        for (int st = 128; st > 0; st >>= 1) {
            if (tid < st) red[tid] += red[tid + st];
            __syncthreads();
        }
        if (tid == 0) atomicAdd(outsum, (double)red[0]);
    }
}

// Cluster scan: grid 32, cluster 16. dir = bx>>4, rank owns hidden [32r,32r+32).
// Fully decentralized: each warp computes its 4 units' gates, assembles an 8B
// bf16x4 packet via shfl, lanes 0-15 push it to the 16 peers and release-arrive.
// mbarrier count = 128 (16 CTAs x 8 warps). No intra-CTA barrier in the loop.
__global__ __launch_bounds__(256, 1) void lstm_scan_cluster(
    const float* __restrict__ Whh, const float* __restrict__ Agate,
    float* __restrict__ outbuf, __nv_bfloat16* __restrict__ xout)
{
    __shared__ uint32_t sh_hp[2][256];
    __shared__ __align__(8) uint64_t sh_bar;

    const int tid = threadIdx.x;
    const int w = tid >> 5, lane = tid & 31;
    const int half = lane >> 4, c16 = lane & 15;
    uint32_t rank;
    asm("mov.u32 %0, %%cluster_ctarank;" : "=r"(rank));
    const int dir = blockIdx.x >> 4;
    const bool fwd = (dir == 0);
    const float* Wd = Whh + (size_t)dir * G4 * DN;
    const float* Ad = Agate + (size_t)dir * L1N * G4;

    const uint32_t bar_addr = smem_u32(&sh_bar);
    const uint32_t hp0 = smem_u32(&sh_hp[0][0]);
    const uint32_t hp1 = smem_u32(&sh_hp[1][0]);

    if (tid == 0)
        asm volatile("mbarrier.init.shared.b64 [%0], %1;" :: "r"(bar_addr), "r"(128u) : "memory");
    sh_hp[1][tid] = 0u;

    // weights: rows idx=2j+half -> grow = (idx>>2)*512 + rank*32 + 4w + (idx&3)
    uint32_t wp[8][16];
    #pragma unroll
    for (int j = 0; j < 8; ++j) {
        int idx = 2 * j + half;
        int grow = (idx >> 2) * 512 + rank * 32 + 4 * w + (idx & 3);
        const float* src = Wd + (size_t)grow * DN + c16 * 32;
        #pragma unroll
        for (int q = 0; q < 8; ++q) {
            float4 v = *(const float4*)(src + q * 4);
            wp[j][2 * q]     = packbf(v.x, v.y);
            wp[j][2 * q + 1] = packbf(v.z, v.w);
        }
    }
    const int unit = 4 * w + 2 * c16 + half;      // valid for c16 < 2
    const int brow = rank * 32 + unit;
    __syncthreads();
    asm volatile("barrier.cluster.arrive.aligned;" ::: "memory");
    asm volatile("barrier.cluster.wait.aligned;" ::: "memory");

    float c_state = 0.f;
    uint32_t parity = 0;

    for (int s = 0; s < L1N; ++s) {
        int t = fwd ? s : (L1N - 1 - s);

        float bias[4];
        if (c16 < 2) {
            #pragma unroll
            for (int g = 0; g < 4; ++g)
                bias[g] = Ad[(size_t)t * G4 + g * 512 + brow];
        }

        if (s > 0) { bar_wait_cl(bar_addr, parity); parity ^= 1; }

        int rb = (s + 1) & 1;
        uint32_t hvp[16];
        #pragma unroll
        for (int q = 0; q < 4; ++q) {
            uint4 v = *(const uint4*)&sh_hp[rb][c16 * 16 + q * 4];
            hvp[4 * q + 0] = v.x; hvp[4 * q + 1] = v.y;
            hvp[4 * q + 2] = v.z; hvp[4 * q + 3] = v.w;
        }

        // matvec partials + packed bf16x2 reduce: pv[m] = (sum row 2m, sum row 2m+1)
        uint32_t pv[4];
        #pragma unroll
        for (int m = 0; m < 4; ++m) {
            __nv_bfloat162 accA = __float2bfloat162_rn(0.f), accB = accA;
            #pragma unroll
            for (int k = 0; k < 16; ++k) {
                accA = __hfma2(as_bf2(wp[2 * m][k]),     as_bf2(hvp[k]), accA);
                accB = __hfma2(as_bf2(wp[2 * m + 1][k]), as_bf2(hvp[k]), accB);
            }
            float sa = __low2float(accA) + __high2float(accA);
            float sb = __low2float(accB) + __high2float(accB);
            __nv_bfloat162 p = __float22bfloat162_rn(make_float2(sa, sb));
            #pragma unroll
            for (int off = 1; off < 16; off <<= 1) {
                uint32_t o = __shfl_xor_sync(0xffffffffu, as_u32(p), off);
                p = __hadd2(p, as_bf2(o));
            }
            pv[m] = as_u32(p);
        }

        float h = 0.f;
        if (c16 < 2) {
            float svg[4];
            #pragma unroll
            for (int g = 0; g < 4; ++g) {
                __nv_bfloat162 pg = as_bf2(pv[g]);
                svg[g] = (c16 == 0) ? __low2float(pg) : __high2float(pg);
            }
            float iv = sigm_t(svg[0] + bias[0]);
            float fv = sigm_t(svg[1] + bias[1]);
            float gv = tanh_t(svg[2] + bias[2]);
            float ov = sigm_t(svg[3] + bias[3]);
            c_state = fv * c_state + iv * gv;
            h = ov * tanh_t(c_state);
            size_t off = (size_t)t * 1024 + dir * 512 + rank * 32 + unit;
            outbuf[off] = h;
            xout[off] = __float2bfloat16(h);
        }

        // assemble warp's 4 h values (units 4w..4w+3 from lanes 0,16,1,17) in all lanes
        float h0 = __shfl_sync(0xffffffffu, h, 0);
        float h1 = __shfl_sync(0xffffffffu, h, 16);
        float h2 = __shfl_sync(0xffffffffu, h, 1);
        float h3 = __shfl_sync(0xffffffffu, h, 17);
        uint32_t w0 = packbf(h0, h1), w1 = packbf(h2, h3);

        uint32_t base = ((s & 1) ? hp1 : hp0) + rank * 64 + w * 8;
        if (lane < 16) {
            st_peer_v2(base, (uint32_t)lane, w0, w1);
            arrive_peer(bar_addr, (uint32_t)lane);
        }
    }
    asm volatile("barrier.cluster.arrive.aligned;" ::: "memory");
    asm volatile("barrier.cluster.wait.aligned;" ::: "memory");
}

__global__ void zkl_kernel(const float* __restrict__ eps, __nv_bfloat16* __restrict__ zb) {
    int i = blockIdx.x * 256 + threadIdx.x;
    float m = d_mu[i], pre = d_ps[i];
    float sg = log1pf(expf(pre));
    float zv = fmaf(eps[i], sg, m);
    d_z[i] = zv;
    zb[i] = __float2bfloat16(zv);
    float term = 0.5f * (sg * sg + m * m - 1.f) - logf(sg);
    __shared__ float red[256];
    red[threadIdx.x] = term;
    __syncthreads();
    for (int st = 128; st > 0; st >>= 1) {
        if (threadIdx.x < st) red[threadIdx.x] += red[threadIdx.x + st];
        __syncthreads();
    }
    if (threadIdx.x == 0) atomicAdd(d_kl, (double)red[0]);
}

__global__ void pos_kernel(const int* __restrict__ en, const float* __restrict__ E) {
    int t = blockIdx.x, tid = threadIdx.x;
    float4 a = *(const float4*)(d_z + t * DN + tid * 4);
    float4 b = *(const float4*)(E + (size_t)en[t] * DN + tid * 4);
    float s = a.x * b.x + a.y * b.y + a.z * b.z + a.w * b.w;
    #pragma unroll
    for (int off = 16; off > 0; off >>= 1) s += __shfl_xor_sync(0xffffffffu, s, off);
    __shared__ float red[4];
    if ((tid & 31) == 0) red[tid >> 5] = s;
    __syncthreads();
    if (tid == 0) d_pos[t] = expf(red[0] + red[1] + red[2] + red[3]);
}

__global__ void final_kernel(float* __restrict__ out) {
    int tid = threadIdx.x;
    float sx = 0.f;
    for (int t = tid; t < 1024; t += 256) {
        float pv = d_pos[t];
        sx += pv / (pv + d_neg[t]);
    }
    __shared__ float red[256];
    red[tid] = sx;
    __syncthreads();
    for (int st = 128; st > 0; st >>= 1) {
        if (tid < st) red[tid] += red[tid + st];
        __syncthreads();
    }
    if (tid == 0) {
        float sum_y = (float)(d_sumy[0] / 1024.0);
        out[0] = -(red[0] + sum_y - (float)d_kl[0]);
    }
}

extern "C" void kernel_launch(void* const* d_in, const int* in_sizes, int n_in,
                              void* d_out, int out_size)
{
    (void)in_sizes; (void)n_in; (void)out_size;
    const int*   en     = (const int*)d_in[0];
    const int*   fr     = (const int*)d_in[1];
    const int*   en_neg = (const int*)d_in[2];
    const int*   fr_neg = (const int*)d_in[3];
    const float* emb    = (const float*)d_in[4];
    const float* Wih[3] = {(const float*)d_in[5], (const float*)d_in[8], (const float*)d_in[11]};
    const float* Whh[3] = {(const float*)d_in[6], (const float*)d_in[9], (const float*)d_in[12]};
    const float* bb[3]  = {(const float*)d_in[7], (const float*)d_in[10], (const float*)d_in[13]};
    const float* Wmu1 = (const float*)d_in[14];
    const float* bmu1 = (const float*)d_in[15];
    const float* Wmu2 = (const float*)d_in[16];
    const float* bmu2 = (const float*)d_in[17];
    const float* Ws1  = (const float*)d_in[18];
    const float* bs1  = (const float*)d_in[19];
    const float* Ws2  = (const float*)d_in[20];
    const float* bs2  = (const float*)d_in[21];
    const float* E_en = (const float*)d_in[22];
    const float* E_fr = (const float*)d_in[23];
    const float* eps  = (const float*)d_in[24];

    float *buf0, *buf1, *Abuf, *mu, *ps, *z, *negp, *negfp;
    double *sumy;
    __nv_bfloat16 *Wb, *Xb, *Gen, *Gfrn, *Gfr, *zb, *hb, *t1b, *t2b, *Wm;
    cudaGetSymbolAddress((void**)&buf0, d_buf0);
    cudaGetSymbolAddress((void**)&buf1, d_buf1);
    cudaGetSymbolAddress((void**)&Abuf, d_A);
    cudaGetSymbolAddress((void**)&mu, d_mu);
    cudaGetSymbolAddress((void**)&ps, d_ps);
    cudaGetSymbolAddress((void**)&z, d_z);
    cudaGetSymbolAddress((void**)&negp, d_neg);
    cudaGetSymbolAddress((void**)&negfp, d_negf);
    cudaGetSymbolAddress((void**)&sumy, d_sumy);
    cudaGetSymbolAddress((void**)&Wb, b_Wb);
    cudaGetSymbolAddress((void**)&Xb, b_Xb);
    cudaGetSymbolAddress((void**)&Gen, b_Gen);
    cudaGetSymbolAddress((void**)&Gfrn, b_Gfrn);
    cudaGetSymbolAddress((void**)&Gfr, b_Gfr);
    cudaGetSymbolAddress((void**)&zb, b_zb);
    cudaGetSymbolAddress((void**)&hb, b_hb);
    cudaGetSymbolAddress((void**)&t1b, b_t1);
    cudaGetSymbolAddress((void**)&t2b, b_t2);
    cudaGetSymbolAddress((void**)&Wm, b_Wm);

    cudaFuncSetAttribute(lstm_scan_cluster,
                         cudaFuncAttributeNonPortableClusterSizeAllowed, 1);

    reset_kernel<<<4, 256>>>();
    gatherb_kernel<<<1024, 128>>>(emb, en, Xb);
    gatherb_kernel<<<8192, 128>>>(E_en, en_neg, Gen);
    gatherb_kernel<<<8192, 128>>>(E_fr, fr_neg, Gfrn);
    gatherb_kernel<<<1024, 128>>>(E_fr, fr, Gfr);

    float* outb[3] = {buf1, buf0, buf1};
    int    Kl[3]   = {512, 1024, 1024};
    for (int l = 0; l < 3; ++l) {
        convb_kernel<<<(2 * 2048 * Kl[l] / 4 + 255) / 256, 256>>>(Wih[l], Wb, 2 * 2048 * Kl[l] / 4);
        for (int d = 0; d < 2; ++d) {
            gemm_bf16_kernel<<<dim3(32, 16), 256>>>(
                Xb, Kl[l], Wb + (size_t)d * 2048 * Kl[l], Kl[l],
                bb[l] + d * 2048,
                Abuf + (size_t)d * 1024 * 2048, nullptr, 2048, Kl[l], 0,
                nullptr, nullptr, nullptr);
        }
        cudaLaunchConfig_t cfg = {};
        cfg.gridDim = dim3(32, 1, 1);
        cfg.blockDim = dim3(256, 1, 1);
        cfg.dynamicSmemBytes = 0;
        cfg.stream = 0;
        cudaLaunchAttribute at[1];
        at[0].id = cudaLaunchAttributeClusterDimension;
        at[0].val.clusterDim.x = 16;
        at[0].val.clusterDim.y = 1;
        at[0].val.clusterDim.z = 1;
        cfg.attrs = at;
        cfg.numAttrs = 1;
        cudaLaunchKernelEx(&cfg, lstm_scan_cluster, Whh[l], (const float*)Abuf, outb[l], Xb);
    }
    hsum_kernel<<<2048, 256>>>(hb);

    convb_kernel<<<256, 256>>>(Wmu1, Wm + 0 * 262144, 65536);
    convb_kernel<<<256, 256>>>(Wmu2, Wm + 1 * 262144, 65536);
    convb_kernel<<<256, 256>>>(Ws1,  Wm + 2 * 262144, 65536);
    convb_kernel<<<256, 256>>>(Ws2,  Wm + 3 * 262144, 65536);

    gemm_bf16_kernel<<<dim3(8, 16), 256>>>(hb, 512, Wm + 0 * 262144, 512, bmu1,
        nullptr, t1b, 512, 512, 1, nullptr, nullptr, nullptr);
    gemm_bf16_kernel<<<dim3(8, 16), 256>>>(t1b, 512, Wm + 1 * 262144, 512, bmu2,
        mu, nullptr, 512, 512, 0, nullptr, nullptr, nullptr);
    gemm_bf16_kernel<<<dim3(8, 16), 256>>>(hb, 512, Wm + 2 * 262144, 512, bs1,
        nullptr, t2b, 512, 512, 1, nullptr, nullptr, nullptr);
    gemm_bf16_kernel<<<dim3(8, 16), 256>>>(t2b, 512, Wm + 3 * 262144, 512, bs2,
        ps, nullptr, 512, 512, 0, nullptr, nullptr, nullptr);

    zkl_kernel<<<2048, 256>>>(eps, zb);
    pos_kernel<<<1024, 128>>>(en, E_en);

    gemm_bf16_kernel<<<dim3(128, 16), 256>>>(zb, 512, Gen, 512, nullptr,
        nullptr, nullptr, 0, 512, 2, nullptr, negp, nullptr);
    gemm_bf16_kernel<<<dim3(128, 16), 256>>>(zb, 512, Gfrn, 512, nullptr,
        nullptr, nullptr, 0, 512, 2, nullptr, negfp, nullptr);
    gemm_bf16_kernel<<<dim3(16, 16), 256>>>(zb, 512, Gfr, 512, nullptr,
        nullptr, nullptr, 0, 512, 3, negfp, nullptr, sumy);

    final_kernel<<<1, 256>>>((float*)d_out);
}

// round 13
// speedup vs baseline: 1.6964x; 1.6964x over previous
#include <cuda_runtime.h>
#include <cuda_bf16.h>
#include <cstdint>
#include <cstring>

#define L1N 1024
#define DN  512
#define G4  2048

__device__ float d_buf0[1024 * 1024];
__device__ float d_buf1[1024 * 1024];
__device__ float d_A[2 * 1024 * 2048];
__device__ float d_mu[1024 * 512];
__device__ float d_ps[1024 * 512];
__device__ float d_z[1024 * 512];
__device__ float d_pos[1024];
__device__ float d_neg[1024];
__device__ float d_negf[1024];
__device__ double d_kl[1];
__device__ double d_sumy[1];

__device__ __nv_bfloat16 b_Wb[2 * 2048 * 1024];
__device__ __nv_bfloat16 b_Xb[1024 * 1024];
__device__ __nv_bfloat16 b_Gen[8192 * 512];
__device__ __nv_bfloat16 b_Gfrn[8192 * 512];
__device__ __nv_bfloat16 b_Gfr[1024 * 512];
__device__ __nv_bfloat16 b_zb[1024 * 512];
__device__ __nv_bfloat16 b_hb[1024 * 512];
__device__ __nv_bfloat16 b_t1[1024 * 512];
__device__ __nv_bfloat16 b_t2[1024 * 512];
__device__ __nv_bfloat16 b_Wm[4 * 512 * 512];

__device__ __forceinline__ float tanh_t(float x) {
    float r;
    asm("tanh.approx.f32 %0, %1;" : "=f"(r) : "f"(x));
    return r;
}
__device__ __forceinline__ float sigm_t(float x) {
    return fmaf(tanh_t(0.5f * x), 0.5f, 0.5f);
}
__device__ __forceinline__ uint32_t smem_u32(const void* p) {
    uint32_t a;
    asm("{ .reg .u64 t; cvta.to.shared.u64 t, %1; cvt.u32.u64 %0, t; }" : "=r"(a) : "l"(p));
    return a;
}
__device__ __forceinline__ __nv_bfloat162 as_bf2(uint32_t v) {
    __nv_bfloat162 r; memcpy(&r, &v, 4); return r;
}
__device__ __forceinline__ uint32_t as_u32(__nv_bfloat162 v) {
    uint32_t r; memcpy(&r, &v, 4); return r;
}
__device__ __forceinline__ uint32_t packbf(float a, float b) {
    __nv_bfloat162 t = __float22bfloat162_rn(make_float2(a, b));
    uint32_t v; memcpy(&v, &t, 4); return v;
}
__device__ __forceinline__ void bar_wait_cl(uint32_t addr, uint32_t par) {
    uint32_t done;
    do {
        asm volatile("{\n\t.reg .pred p;\n\t"
            "mbarrier.try_wait.parity.acquire.cluster.shared::cta.b64 p, [%1], %2, 0x989680;\n\t"
            "selp.b32 %0, 1, 0, p;\n\t}"
            : "=r"(done) : "r"(addr), "r"(par) : "memory");
    } while (!done);
}
__device__ __forceinline__ void arrive_peer(uint32_t addr, uint32_t rank) {
    asm volatile("{\n\t.reg .b32 ra;\n\t"
        "mapa.shared::cluster.u32 ra, %0, %1;\n\t"
        "mbarrier.arrive.shared::cluster.b64 _, [ra];\n\t}"
        :: "r"(addr), "r"(rank) : "memory");
}
__device__ __forceinline__ void st_peer_v4(uint32_t addr, uint32_t peer, uint4 v) {
    asm volatile("{\n\t.reg .b32 ra;\n\t"
        "mapa.shared::cluster.u32 ra, %0, %1;\n\t"
        "st.shared::cluster.v4.u32 [ra], {%2,%3,%4,%5};\n\t}"
        :: "r"(addr), "r"(peer), "r"(v.x), "r"(v.y), "r"(v.z), "r"(v.w) : "memory");
}
__device__ __forceinline__ void ldsm_x4(uint32_t& r0, uint32_t& r1, uint32_t& r2, uint32_t& r3, uint32_t addr) {
    asm volatile("ldmatrix.sync.aligned.m8n8.x4.shared.b16 {%0,%1,%2,%3}, [%4];"
        : "=r"(r0), "=r"(r1), "=r"(r2), "=r"(r3) : "r"(addr));
}
__device__ __forceinline__ void ldsm_x2(uint32_t& r0, uint32_t& r1, uint32_t addr) {
    asm volatile("ldmatrix.sync.aligned.m8n8.x2.shared.b16 {%0,%1}, [%2];"
        : "=r"(r0), "=r"(r1) : "r"(addr));
}
__device__ __forceinline__ void mma16816(float* d, const uint32_t* a, const uint32_t* b) {
    asm volatile("mma.sync.aligned.m16n8k16.row.col.f32.bf16.bf16.f32 "
        "{%0,%1,%2,%3}, {%4,%5,%6,%7}, {%8,%9}, {%0,%1,%2,%3};"
        : "+f"(d[0]), "+f"(d[1]), "+f"(d[2]), "+f"(d[3])
        : "r"(a[0]), "r"(a[1]), "r"(a[2]), "r"(a[3]), "r"(b[0]), "r"(b[1]));
}

__global__ void reset_kernel() {
    int i = blockIdx.x * 256 + threadIdx.x;
    if (i < 1024) { d_neg[i] = 0.f; d_negf[i] = 0.f; }
    if (i == 0) { d_kl[0] = 0.0; d_sumy[0] = 0.0; }
}

__global__ void gatherb_kernel(const float* __restrict__ E, const int* __restrict__ idx,
                               __nv_bfloat16* __restrict__ dst) {
    int r = blockIdx.x, t = threadIdx.x;  // 128 threads
    float4 v = *(const float4*)(E + (size_t)idx[r] * 512 + t * 4);
    ((uint2*)(dst + (size_t)r * 512))[t] = make_uint2(packbf(v.x, v.y), packbf(v.z, v.w));
}

__global__ void convb_kernel(const float* __restrict__ src, __nv_bfloat16* __restrict__ dst, int n4) {
    int i = blockIdx.x * 256 + threadIdx.x;
    if (i < n4) {
        float4 v = ((const float4*)src)[i];
        ((uint2*)dst)[i] = make_uint2(packbf(v.x, v.y), packbf(v.z, v.w));
    }
}

__global__ void hsum_kernel(__nv_bfloat16* __restrict__ hb) {
    int i = blockIdx.x * 256 + threadIdx.x;  // 524288
    int t = i >> 9, d = i & 511;
    hb[i] = __float2bfloat16(d_buf1[t * 1024 + d] + d_buf1[t * 1024 + 512 + d]);
}

// bf16 tensor-core GEMM: C[M][N] = A[M][K] @ B[N][K]^T (fp32 accum)
__global__ __launch_bounds__(256) void gemm_bf16_kernel(
    const __nv_bfloat16* __restrict__ A, int lda,
    const __nv_bfloat16* __restrict__ B, int ldb,
    const float* __restrict__ bias,
    float* __restrict__ C, __nv_bfloat16* __restrict__ Cb, int ldc,
    int K, int mode,
    const float* __restrict__ negf,
    float* __restrict__ rowsum,
    double* __restrict__ outsum)
{
    __shared__ __align__(16) __nv_bfloat16 As[64][40];
    __shared__ __align__(16) __nv_bfloat16 Bs[64][40];
    __shared__ float red[256];

    int tid = threadIdx.x;
    int wid = tid >> 5, lane = tid & 31;
    int m0 = blockIdx.y * 64, n0 = blockIdx.x * 64;
    int wm = (wid & 1) * 32, wn = (wid >> 1) * 16;
    int lr = tid >> 2, ls = (tid & 3) * 8;

    float acc[2][2][4] = {};

    uint32_t a_addr[2], b_addr[2];
    #pragma unroll
    for (int i = 0; i < 2; ++i)
        a_addr[i] = smem_u32(&As[wm + i * 16 + (lane & 15)][(lane >> 4) * 8]);
    #pragma unroll
    for (int j = 0; j < 2; ++j)
        b_addr[j] = smem_u32(&Bs[wn + j * 8 + (lane & 7)][((lane >> 3) & 1) * 8]);

    for (int k0 = 0; k0 < K; k0 += 32) {
        *(uint4*)&As[lr][ls] = *(const uint4*)(A + (size_t)(m0 + lr) * lda + k0 + ls);
        *(uint4*)&Bs[lr][ls] = *(const uint4*)(B + (size_t)(n0 + lr) * ldb + k0 + ls);
        __syncthreads();
        #pragma unroll
        for (int kk = 0; kk < 2; ++kk) {
            uint32_t af[2][4], bf[2][2];
            #pragma unroll
            for (int i = 0; i < 2; ++i)
                ldsm_x4(af[i][0], af[i][1], af[i][2], af[i][3], a_addr[i] + kk * 32);
            #pragma unroll
            for (int j = 0; j < 2; ++j)
                ldsm_x2(bf[j][0], bf[j][1], b_addr[j] + kk * 32);
            #pragma unroll
            for (int i = 0; i < 2; ++i)
                #pragma unroll
                for (int j = 0; j < 2; ++j)
                    mma16816(acc[i][j], af[i], bf[j]);
        }
        __syncthreads();
    }

    int qr = lane >> 2, qc = (lane & 3) * 2;
    if (mode <= 1) {
        #pragma unroll
        for (int i = 0; i < 2; ++i)
            #pragma unroll
            for (int r = 0; r < 2; ++r) {
                int row = m0 + wm + i * 16 + r * 8 + qr;
                #pragma unroll
                for (int j = 0; j < 2; ++j) {
                    int col = n0 + wn + j * 8 + qc;
                    float v0 = acc[i][j][r * 2 + 0] + (bias ? bias[col] : 0.f);
                    float v1 = acc[i][j][r * 2 + 1] + (bias ? bias[col + 1] : 0.f);
                    if (mode == 1) { v0 = fmaxf(v0, 0.f); v1 = fmaxf(v1, 0.f); }
                    if (C) *(float2*)(C + (size_t)row * ldc + col) = make_float2(v0, v1);
                    if (Cb) *(uint32_t*)(Cb + (size_t)row * ldc + col) = packbf(v0, v1);
                }
            }
    } else if (mode == 2) {
        #pragma unroll
        for (int i = 0; i < 2; ++i)
            #pragma unroll
            for (int r = 0; r < 2; ++r) {
                float s = 0.f;
                #pragma unroll
                for (int j = 0; j < 2; ++j)
                    s += __expf(acc[i][j][r * 2]) + __expf(acc[i][j][r * 2 + 1]);
                s += __shfl_xor_sync(0xffffffffu, s, 1);
                s += __shfl_xor_sync(0xffffffffu, s, 2);
                if ((lane & 3) == 0)
                    atomicAdd(rowsum + m0 + wm + i * 16 + r * 8 + qr, s);
            }
    } else {
        float ssum = 0.f;
        #pragma unroll
        for (int i = 0; i < 2; ++i)
            #pragma unroll
            for (int r = 0; r < 2; ++r) {
                float nf = negf[m0 + wm + i * 16 + r * 8 + qr];
                #pragma unroll
                for (int j = 0; j < 2; ++j) {
                    float e0 = __expf(acc[i][j][r * 2]);
                    float e1 = __expf(acc[i][j][r * 2 + 1]);
                    ssum += e0 / (e0 + nf) + e1 / (e1 + nf);
                }
            }
        red[tid] = ssum;
        __syncthreads();
        for (int st = 128; st > 0; st >>= 1) {
            if (tid < st) red[tid] += red[tid + st];
            __syncthreads();
        }
        if (tid == 0) atomicAdd(outsum, (double)red[0]);
    }
}

// Cluster scan (round-11 skeleton + packed bf16x2 reduce): grid 32, cluster 16.
// dir = bx>>4, rank owns hidden [32r,32r+32). Rows idx=2j+half; warp w owns units
// 4w..4w+3 (all 4 gates). Gate lanes c16<2 compute unit = 4w+2*c16+half.
// Staging in sh_wb -> one __syncthreads -> warp-0 v4 broadcast -> 16 arrives.
__global__ __launch_bounds__(256, 1) void lstm_scan_cluster(
    const float* __restrict__ Whh, const float* __restrict__ Agate,
    float* __restrict__ outbuf, __nv_bfloat16* __restrict__ xout)
{
    __shared__ uint32_t sh_hp[2][256];
    __shared__ __align__(16) __nv_bfloat16 sh_wb[32];
    __shared__ __align__(8) uint64_t sh_bar;

    const int tid = threadIdx.x;
    const int w = tid >> 5, lane = tid & 31;
    const int half = lane >> 4, c16 = lane & 15;
    uint32_t rank;
    asm("mov.u32 %0, %%cluster_ctarank;" : "=r"(rank));
    const int dir = blockIdx.x >> 4;
    const bool fwd = (dir == 0);
    const float* Wd = Whh + (size_t)dir * G4 * DN;
    const float* Ad = Agate + (size_t)dir * L1N * G4;

    const uint32_t bar_addr = smem_u32(&sh_bar);
    const uint32_t hp0 = smem_u32(&sh_hp[0][0]);
    const uint32_t hp1 = smem_u32(&sh_hp[1][0]);

    if (tid == 0)
        asm volatile("mbarrier.init.shared.b64 [%0], %1;" :: "r"(bar_addr), "r"(16u) : "memory");
    sh_hp[1][tid] = 0u;

    // weights: rows idx=2j+half -> grow = (idx>>2)*512 + rank*32 + 4w + (idx&3)
    uint32_t wp[8][16];
    #pragma unroll
    for (int j = 0; j < 8; ++j) {
        int idx = 2 * j + half;
        int grow = (idx >> 2) * 512 + rank * 32 + 4 * w + (idx & 3);
        const float* src = Wd + (size_t)grow * DN + c16 * 32;
        #pragma unroll
        for (int q = 0; q < 8; ++q) {
            float4 v = *(const float4*)(src + q * 4);
            wp[j][2 * q]     = packbf(v.x, v.y);
            wp[j][2 * q + 1] = packbf(v.z, v.w);
        }
    }
    const int unit = 4 * w + 2 * c16 + half;      // valid for c16 < 2
    const int brow = rank * 32 + unit;
    __syncthreads();
    asm volatile("barrier.cluster.arrive.aligned;" ::: "memory");
    asm volatile("barrier.cluster.wait.aligned;" ::: "memory");

    float c_state = 0.f;
    uint32_t parity = 0;

    for (int s = 0; s < L1N; ++s) {
        int t = fwd ? s : (L1N - 1 - s);

        float bias[4];
        if (c16 < 2) {
            #pragma unroll
            for (int g = 0; g < 4; ++g)
                bias[g] = Ad[(size_t)t * G4 + g * 512 + brow];
        }

        if (s > 0) { bar_wait_cl(bar_addr, parity); parity ^= 1; }

        int rb = (s + 1) & 1;
        uint32_t hvp[16];
        #pragma unroll
        for (int q = 0; q < 4; ++q) {
            uint4 v = *(const uint4*)&sh_hp[rb][c16 * 16 + q * 4];
            hvp[4 * q + 0] = v.x; hvp[4 * q + 1] = v.y;
            hvp[4 * q + 2] = v.z; hvp[4 * q + 3] = v.w;
        }

        // matvec partials + packed bf16x2 butterfly: pv[m] = (sum row 2m, sum row 2m+1)
        uint32_t pv[4];
        #pragma unroll
        for (int m = 0; m < 4; ++m) {
            __nv_bfloat162 accA = __float2bfloat162_rn(0.f), accB = accA;
            #pragma unroll
            for (int k = 0; k < 16; ++k) {
                accA = __hfma2(as_bf2(wp[2 * m][k]),     as_bf2(hvp[k]), accA);
                accB = __hfma2(as_bf2(wp[2 * m + 1][k]), as_bf2(hvp[k]), accB);
            }
            float sa = __low2float(accA) + __high2float(accA);
            float sb = __low2float(accB) + __high2float(accB);
            __nv_bfloat162 p = __float22bfloat162_rn(make_float2(sa, sb));
            #pragma unroll
            for (int off = 1; off < 16; off <<= 1) {
                uint32_t o = __shfl_xor_sync(0xffffffffu, as_u32(p), off);
                p = __hadd2(p, as_bf2(o));
            }
            pv[m] = as_u32(p);
        }

        if (c16 < 2) {
            float svg[4];
            #pragma unroll
            for (int g = 0; g < 4; ++g) {
                __nv_bfloat162 pg = as_bf2(pv[g]);
                svg[g] = (c16 == 0) ? __low2float(pg) : __high2float(pg);
            }
            float iv = sigm_t(svg[0] + bias[0]);
            float fv = sigm_t(svg[1] + bias[1]);
            float gv = tanh_t(svg[2] + bias[2]);
            float ov = sigm_t(svg[3] + bias[3]);
            c_state = fv * c_state + iv * gv;
            float h = ov * tanh_t(c_state);
            __nv_bfloat16 hb16 = __float2bfloat16(h);
            sh_wb[unit] = hb16;
            size_t off = (size_t)t * 1024 + dir * 512 + rank * 32 + unit;
            outbuf[off] = h;
            xout[off] = hb16;
        }
        __syncthreads();

        if (w == 0) {
            uint32_t base = ((s & 1) ? hp1 : hp0) + rank * 64;
            uint4 v0 = ((const uint4*)sh_wb)[2 * half];
            uint4 v1 = ((const uint4*)sh_wb)[2 * half + 1];
            st_peer_v4(base + (2 * half) * 16,     (uint32_t)c16, v0);
            st_peer_v4(base + (2 * half + 1) * 16, (uint32_t)c16, v1);
            __syncwarp();
            if (lane < 16) arrive_peer(bar_addr, (uint32_t)lane);
        }
    }
    asm volatile("barrier.cluster.arrive.aligned;" ::: "memory");
    asm volatile("barrier.cluster.wait.aligned;" ::: "memory");
}

__global__ void zkl_kernel(const float* __restrict__ eps, __nv_bfloat16* __restrict__ zb) {
    int i = blockIdx.x * 256 + threadIdx.x;
    float m = d_mu[i], pre = d_ps[i];
    float sg = log1pf(expf(pre));
    float zv = fmaf(eps[i], sg, m);
    d_z[i] = zv;
    zb[i] = __float2bfloat16(zv);
    float term = 0.5f * (sg * sg + m * m - 1.f) - logf(sg);
    __shared__ float red[256];
    red[threadIdx.x] = term;
    __syncthreads();
    for (int st = 128; st > 0; st >>= 1) {
        if (threadIdx.x < st) red[threadIdx.x] += red[threadIdx.x + st];
        __syncthreads();
    }
    if (threadIdx.x == 0) atomicAdd(d_kl, (double)red[0]);
}

__global__ void pos_kernel(const int* __restrict__ en, const float* __restrict__ E) {
    int t = blockIdx.x, tid = threadIdx.x;
    float4 a = *(const float4*)(d_z + t * DN + tid * 4);
    float4 b = *(const float4*)(E + (size_t)en[t] * DN + tid * 4);
    float s = a.x * b.x + a.y * b.y + a.z * b.z + a.w * b.w;
    #pragma unroll
    for (int off = 16; off > 0; off >>= 1) s += __shfl_xor_sync(0xffffffffu, s, off);
    __shared__ float red[4];
    if ((tid & 31) == 0) red[tid >> 5] = s;
    __syncthreads();
    if (tid == 0) d_pos[t] = expf(red[0] + red[1] + red[2] + red[3]);
}

__global__ void final_kernel(float* __restrict__ out) {
    int tid = threadIdx.x;
    float sx = 0.f;
    for (int t = tid; t < 1024; t += 256) {
        float pv = d_pos[t];
        sx += pv / (pv + d_neg[t]);
    }
    __shared__ float red[256];
    red[tid] = sx;
    __syncthreads();
    for (int st = 128; st > 0; st >>= 1) {
        if (tid < st) red[tid] += red[tid + st];
        __syncthreads();
    }
    if (tid == 0) {
        float sum_y = (float)(d_sumy[0] / 1024.0);
        out[0] = -(red[0] + sum_y - (float)d_kl[0]);
    }
}

extern "C" void kernel_launch(void* const* d_in, const int* in_sizes, int n_in,
                              void* d_out, int out_size)
{
    (void)in_sizes; (void)n_in; (void)out_size;
    const int*   en     = (const int*)d_in[0];
    const int*   fr     = (const int*)d_in[1];
    const int*   en_neg = (const int*)d_in[2];
    const int*   fr_neg = (const int*)d_in[3];
    const float* emb    = (const float*)d_in[4];
    const float* Wih[3] = {(const float*)d_in[5], (const float*)d_in[8], (const float*)d_in[11]};
    const float* Whh[3] = {(const float*)d_in[6], (const float*)d_in[9], (const float*)d_in[12]};
    const float* bb[3]  = {(const float*)d_in[7], (const float*)d_in[10], (const float*)d_in[13]};
    const float* Wmu1 = (const float*)d_in[14];
    const float* bmu1 = (const float*)d_in[15];
    const float* Wmu2 = (const float*)d_in[16];
    const float* bmu2 = (const float*)d_in[17];
    const float* Ws1  = (const float*)d_in[18];
    const float* bs1  = (const float*)d_in[19];
    const float* Ws2  = (const float*)d_in[20];
    const float* bs2  = (const float*)d_in[21];
    const float* E_en = (const float*)d_in[22];
    const float* E_fr = (const float*)d_in[23];
    const float* eps  = (const float*)d_in[24];

    float *buf0, *buf1, *Abuf, *mu, *ps, *z, *negp, *negfp;
    double *sumy;
    __nv_bfloat16 *Wb, *Xb, *Gen, *Gfrn, *Gfr, *zb, *hb, *t1b, *t2b, *Wm;
    cudaGetSymbolAddress((void**)&buf0, d_buf0);
    cudaGetSymbolAddress((void**)&buf1, d_buf1);
    cudaGetSymbolAddress((void**)&Abuf, d_A);
    cudaGetSymbolAddress((void**)&mu, d_mu);
    cudaGetSymbolAddress((void**)&ps, d_ps);
    cudaGetSymbolAddress((void**)&z, d_z);
    cudaGetSymbolAddress((void**)&negp, d_neg);
    cudaGetSymbolAddress((void**)&negfp, d_negf);
    cudaGetSymbolAddress((void**)&sumy, d_sumy);
    cudaGetSymbolAddress((void**)&Wb, b_Wb);
    cudaGetSymbolAddress((void**)&Xb, b_Xb);
    cudaGetSymbolAddress((void**)&Gen, b_Gen);
    cudaGetSymbolAddress((void**)&Gfrn, b_Gfrn);
    cudaGetSymbolAddress((void**)&Gfr, b_Gfr);
    cudaGetSymbolAddress((void**)&zb, b_zb);
    cudaGetSymbolAddress((void**)&hb, b_hb);
    cudaGetSymbolAddress((void**)&t1b, b_t1);
    cudaGetSymbolAddress((void**)&t2b, b_t2);
    cudaGetSymbolAddress((void**)&Wm, b_Wm);

    cudaFuncSetAttribute(lstm_scan_cluster,
                         cudaFuncAttributeNonPortableClusterSizeAllowed, 1);

    reset_kernel<<<4, 256>>>();
    gatherb_kernel<<<1024, 128>>>(emb, en, Xb);
    gatherb_kernel<<<8192, 128>>>(E_en, en_neg, Gen);
    gatherb_kernel<<<8192, 128>>>(E_fr, fr_neg, Gfrn);
    gatherb_kernel<<<1024, 128>>>(E_fr, fr, Gfr);

    float* outb[3] = {buf1, buf0, buf1};
    int    Kl[3]   = {512, 1024, 1024};
    for (int l = 0; l < 3; ++l) {
        convb_kernel<<<(2 * 2048 * Kl[l] / 4 + 255) / 256, 256>>>(Wih[l], Wb, 2 * 2048 * Kl[l] / 4);
        for (int d = 0; d < 2; ++d) {
            gemm_bf16_kernel<<<dim3(32, 16), 256>>>(
                Xb, Kl[l], Wb + (size_t)d * 2048 * Kl[l], Kl[l],
                bb[l] + d * 2048,
                Abuf + (size_t)d * 1024 * 2048, nullptr, 2048, Kl[l], 0,
                nullptr, nullptr, nullptr);
        }
        cudaLaunchConfig_t cfg = {};
        cfg.gridDim = dim3(32, 1, 1);
        cfg.blockDim = dim3(256, 1, 1);
        cfg.dynamicSmemBytes = 0;
        cfg.stream = 0;
        cudaLaunchAttribute at[1];
        at[0].id = cudaLaunchAttributeClusterDimension;
        at[0].val.clusterDim.x = 16;
        at[0].val.clusterDim.y = 1;
        at[0].val.clusterDim.z = 1;
        cfg.attrs = at;
        cfg.numAttrs = 1;
        cudaLaunchKernelEx(&cfg, lstm_scan_cluster, Whh[l], (const float*)Abuf, outb[l], Xb);
    }
    hsum_kernel<<<2048, 256>>>(hb);

    convb_kernel<<<256, 256>>>(Wmu1, Wm + 0 * 262144, 65536);
    convb_kernel<<<256, 256>>>(Wmu2, Wm + 1 * 262144, 65536);
    convb_kernel<<<256, 256>>>(Ws1,  Wm + 2 * 262144, 65536);
    convb_kernel<<<256, 256>>>(Ws2,  Wm + 3 * 262144, 65536);

    gemm_bf16_kernel<<<dim3(8, 16), 256>>>(hb, 512, Wm + 0 * 262144, 512, bmu1,
        nullptr, t1b, 512, 512, 1, nullptr, nullptr, nullptr);
    gemm_bf16_kernel<<<dim3(8, 16), 256>>>(t1b, 512, Wm + 1 * 262144, 512, bmu2,
        mu, nullptr, 512, 512, 0, nullptr, nullptr, nullptr);
    gemm_bf16_kernel<<<dim3(8, 16), 256>>>(hb, 512, Wm + 2 * 262144, 512, bs1,
        nullptr, t2b, 512, 512, 1, nullptr, nullptr, nullptr);
    gemm_bf16_kernel<<<dim3(8, 16), 256>>>(t2b, 512, Wm + 3 * 262144, 512, bs2,
        ps, nullptr, 512, 512, 0, nullptr, nullptr, nullptr);

    zkl_kernel<<<2048, 256>>>(eps, zb);
    pos_kernel<<<1024, 128>>>(en, E_en);

    gemm_bf16_kernel<<<dim3(128, 16), 256>>>(zb, 512, Gen, 512, nullptr,
        nullptr, nullptr, 0, 512, 2, nullptr, negp, nullptr);
    gemm_bf16_kernel<<<dim3(128, 16), 256>>>(zb, 512, Gfrn, 512, nullptr,
        nullptr, nullptr, 0, 512, 2, nullptr, negfp, nullptr);
    gemm_bf16_kernel<<<dim3(16, 16), 256>>>(zb, 512, Gfr, 512, nullptr,
        nullptr, nullptr, 0, 512, 3, negfp, nullptr, sumy);

    final_kernel<<<1, 256>>>((float*)d_out);
}

// round 16
// speedup vs baseline: 1.7988x; 1.0603x over previous
#include <cuda_runtime.h>
#include <cuda_bf16.h>
#include <cstdint>
#include <cstring>

#define L1N 1024
#define DN  512
#define G4  2048

__device__ float d_buf0[1024 * 1024];
__device__ float d_buf1[1024 * 1024];
__device__ float d_A[2 * 1024 * 2048];
__device__ float d_mu[1024 * 512];
__device__ float d_ps[1024 * 512];
__device__ float d_z[1024 * 512];
__device__ float d_pos[1024];
__device__ float d_neg[1024];
__device__ float d_negf[1024];
__device__ double d_kl[1];
__device__ double d_sumy[1];
__device__ int d_gcnt[3 * 2 * 16];   // per (layer, dir, m-tile) completion counters

__device__ __nv_bfloat16 b_Wb[2 * 2048 * 1024];
__device__ __nv_bfloat16 b_Xb[1024 * 1024];
__device__ __nv_bfloat16 b_Xc[1024 * 1024];
__device__ __nv_bfloat16 b_Gen[8192 * 512];
__device__ __nv_bfloat16 b_Gfrn[8192 * 512];
__device__ __nv_bfloat16 b_Gfr[1024 * 512];
__device__ __nv_bfloat16 b_zb[1024 * 512];
__device__ __nv_bfloat16 b_hb[1024 * 512];
__device__ __nv_bfloat16 b_t1[1024 * 512];
__device__ __nv_bfloat16 b_t2[1024 * 512];
__device__ __nv_bfloat16 b_Wm[4 * 512 * 512];

__device__ __forceinline__ float tanh_t(float x) {
    float r;
    asm("tanh.approx.f32 %0, %1;" : "=f"(r) : "f"(x));
    return r;
}
__device__ __forceinline__ float sigm_t(float x) {
    return fmaf(tanh_t(0.5f * x), 0.5f, 0.5f);
}
__device__ __forceinline__ uint32_t smem_u32(const void* p) {
    uint32_t a;
    asm("{ .reg .u64 t; cvta.to.shared.u64 t, %1; cvt.u32.u64 %0, t; }" : "=r"(a) : "l"(p));
    return a;
}
__device__ __forceinline__ __nv_bfloat162 as_bf2(uint32_t v) {
    __nv_bfloat162 r; memcpy(&r, &v, 4); return r;
}
__device__ __forceinline__ uint32_t as_u32(__nv_bfloat162 v) {
    uint32_t r; memcpy(&r, &v, 4); return r;
}
__device__ __forceinline__ uint32_t packbf(float a, float b) {
    __nv_bfloat162 t = __float22bfloat162_rn(make_float2(a, b));
    uint32_t v; memcpy(&v, &t, 4); return v;
}
__device__ __forceinline__ int ld_acq_i(const int* p) {
    int v;
    asm volatile("ld.acquire.gpu.s32 %0, [%1];" : "=r"(v) : "l"(p) : "memory");
    return v;
}
__device__ __forceinline__ void bar_wait_cl(uint32_t addr, uint32_t par) {
    uint32_t done;
    do {
        asm volatile("{\n\t.reg .pred p;\n\t"
            "mbarrier.try_wait.parity.acquire.cluster.shared::cta.b64 p, [%1], %2, 0x989680;\n\t"
            "selp.b32 %0, 1, 0, p;\n\t}"
            : "=r"(done) : "r"(addr), "r"(par) : "memory");
    } while (!done);
}
__device__ __forceinline__ void arrive_peer(uint32_t addr, uint32_t rank) {
    asm volatile("{\n\t.reg .b32 ra;\n\t"
        "mapa.shared::cluster.u32 ra, %0, %1;\n\t"
        "mbarrier.arrive.shared::cluster.b64 _, [ra];\n\t}"
        :: "r"(addr), "r"(rank) : "memory");
}
__device__ __forceinline__ void st_peer_v4(uint32_t addr, uint32_t peer, uint4 v) {
    asm volatile("{\n\t.reg .b32 ra;\n\t"
        "mapa.shared::cluster.u32 ra, %0, %1;\n\t"
        "st.shared::cluster.v4.u32 [ra], {%2,%3,%4,%5};\n\t}"
        :: "r"(addr), "r"(peer), "r"(v.x), "r"(v.y), "r"(v.z), "r"(v.w) : "memory");
}
__device__ __forceinline__ void ldsm_x4(uint32_t& r0, uint32_t& r1, uint32_t& r2, uint32_t& r3, uint32_t addr) {
    asm volatile("ldmatrix.sync.aligned.m8n8.x4.shared.b16 {%0,%1,%2,%3}, [%4];"
        : "=r"(r0), "=r"(r1), "=r"(r2), "=r"(r3) : "r"(addr));
}
__device__ __forceinline__ void ldsm_x2(uint32_t& r0, uint32_t& r1, uint32_t addr) {
    asm volatile("ldmatrix.sync.aligned.m8n8.x2.shared.b16 {%0,%1}, [%2];"
        : "=r"(r0), "=r"(r1) : "r"(addr));
}
__device__ __forceinline__ void mma16816(float* d, const uint32_t* a, const uint32_t* b) {
    asm volatile("mma.sync.aligned.m16n8k16.row.col.f32.bf16.bf16.f32 "
        "{%0,%1,%2,%3}, {%4,%5,%6,%7}, {%8,%9}, {%0,%1,%2,%3};"
        : "+f"(d[0]), "+f"(d[1]), "+f"(d[2]), "+f"(d[3])
        : "r"(a[0]), "r"(a[1]), "r"(a[2]), "r"(a[3]), "r"(b[0]), "r"(b[1]));
}

__global__ void reset_kernel() {
    int i = blockIdx.x * 256 + threadIdx.x;
    if (i < 1024) { d_neg[i] = 0.f; d_negf[i] = 0.f; }
    if (i < 96) d_gcnt[i] = 0;
    if (i == 0) { d_kl[0] = 0.0; d_sumy[0] = 0.0; }
}

__global__ void gatherb_kernel(const float* __restrict__ E, const int* __restrict__ idx,
                               __nv_bfloat16* __restrict__ dst) {
    int r = blockIdx.x, t = threadIdx.x;  // 128 threads
    float4 v = *(const float4*)(E + (size_t)idx[r] * 512 + t * 4);
    ((uint2*)(dst + (size_t)r * 512))[t] = make_uint2(packbf(v.x, v.y), packbf(v.z, v.w));
}

__global__ void convb_kernel(const float* __restrict__ src, __nv_bfloat16* __restrict__ dst, int n4) {
    int i = blockIdx.x * 256 + threadIdx.x;
    if (i < n4) {
        float4 v = ((const float4*)src)[i];
        ((uint2*)dst)[i] = make_uint2(packbf(v.x, v.y), packbf(v.z, v.w));
    }
}

__global__ void hsum_kernel(__nv_bfloat16* __restrict__ hb) {
    int i = blockIdx.x * 256 + threadIdx.x;  // 524288
    int t = i >> 9, d = i & 511;
    hb[i] = __float2bfloat16(d_buf1[t * 1024 + d] + d_buf1[t * 1024 + 512 + d]);
}

// bf16 tensor-core GEMM: C[M][N] = A[M][K] @ B[N][K]^T (fp32 accum)
// rev: reverse m-tile mapping (bwd-scan production order). cnt: per-m-tile release counters.
__global__ __launch_bounds__(256) void gemm_bf16_kernel(
    const __nv_bfloat16* __restrict__ A, int lda,
    const __nv_bfloat16* __restrict__ B, int ldb,
    const float* __restrict__ bias,
    float* __restrict__ C, __nv_bfloat16* __restrict__ Cb, int ldc,
    int K, int mode,
    const float* __restrict__ negf,
    float* __restrict__ rowsum,
    double* __restrict__ outsum,
    int rev, int* cnt)
{
    __shared__ __align__(16) __nv_bfloat16 As[64][40];
    __shared__ __align__(16) __nv_bfloat16 Bs[64][40];
    __shared__ float red[256];

    int tid = threadIdx.x;
    int wid = tid >> 5, lane = tid & 31;
    int m0 = (rev ? (gridDim.y - 1 - blockIdx.y) : blockIdx.y) * 64;
    int n0 = blockIdx.x * 64;
    int wm = (wid & 1) * 32, wn = (wid >> 1) * 16;
    int lr = tid >> 2, ls = (tid & 3) * 8;

    float acc[2][2][4] = {};

    uint32_t a_addr[2], b_addr[2];
    #pragma unroll
    for (int i = 0; i < 2; ++i)
        a_addr[i] = smem_u32(&As[wm + i * 16 + (lane & 15)][(lane >> 4) * 8]);
    #pragma unroll
    for (int j = 0; j < 2; ++j)
        b_addr[j] = smem_u32(&Bs[wn + j * 8 + (lane & 7)][((lane >> 3) & 1) * 8]);

    for (int k0 = 0; k0 < K; k0 += 32) {
        *(uint4*)&As[lr][ls] = *(const uint4*)(A + (size_t)(m0 + lr) * lda + k0 + ls);
        *(uint4*)&Bs[lr][ls] = *(const uint4*)(B + (size_t)(n0 + lr) * ldb + k0 + ls);
        __syncthreads();
        #pragma unroll
        for (int kk = 0; kk < 2; ++kk) {
            uint32_t af[2][4], bf[2][2];
            #pragma unroll
            for (int i = 0; i < 2; ++i)
                ldsm_x4(af[i][0], af[i][1], af[i][2], af[i][3], a_addr[i] + kk * 32);
            #pragma unroll
            for (int j = 0; j < 2; ++j)
                ldsm_x2(bf[j][0], bf[j][1], b_addr[j] + kk * 32);
            #pragma unroll
            for (int i = 0; i < 2; ++i)
                #pragma unroll
                for (int j = 0; j < 2; ++j)
                    mma16816(acc[i][j], af[i], bf[j]);
        }
        __syncthreads();
    }

    int qr = lane >> 2, qc = (lane & 3) * 2;
    if (mode <= 1) {
        #pragma unroll
        for (int i = 0; i < 2; ++i)
            #pragma unroll
            for (int r = 0; r < 2; ++r) {
                int row = m0 + wm + i * 16 + r * 8 + qr;
                #pragma unroll
                for (int j = 0; j < 2; ++j) {
                    int col = n0 + wn + j * 8 + qc;
                    float v0 = acc[i][j][r * 2 + 0] + (bias ? bias[col] : 0.f);
                    float v1 = acc[i][j][r * 2 + 1] + (bias ? bias[col + 1] : 0.f);
                    if (mode == 1) { v0 = fmaxf(v0, 0.f); v1 = fmaxf(v1, 0.f); }
                    if (C) *(float2*)(C + (size_t)row * ldc + col) = make_float2(v0, v1);
                    if (Cb) *(uint32_t*)(Cb + (size_t)row * ldc + col) = packbf(v0, v1);
                }
            }
        if (cnt) {
            // multi-writer release: every thread fences its own stores, barrier
            // orders all fences before tid0's release-add.
            __threadfence();
            __syncthreads();
            if (tid == 0)
                asm volatile("red.release.gpu.global.add.s32 [%0], 1;"
                             :: "l"(cnt + (m0 >> 6)) : "memory");
        }
    } else if (mode == 2) {
        #pragma unroll
        for (int i = 0; i < 2; ++i)
            #pragma unroll
            for (int r = 0; r < 2; ++r) {
                float s = 0.f;
                #pragma unroll
                for (int j = 0; j < 2; ++j)
                    s += __expf(acc[i][j][r * 2]) + __expf(acc[i][j][r * 2 + 1]);
                s += __shfl_xor_sync(0xffffffffu, s, 1);
                s += __shfl_xor_sync(0xffffffffu, s, 2);
                if ((lane & 3) == 0)
                    atomicAdd(rowsum + m0 + wm + i * 16 + r * 8 + qr, s);
            }
    } else {
        float ssum = 0.f;
        #pragma unroll
        for (int i = 0; i < 2; ++i)
            #pragma unroll
            for (int r = 0; r < 2; ++r) {
                float nf = negf[m0 + wm + i * 16 + r * 8 + qr];
                #pragma unroll
                for (int j = 0; j < 2; ++j) {
                    float e0 = __expf(acc[i][j][r * 2]);
                    float e1 = __expf(acc[i][j][r * 2 + 1]);
                    ssum += e0 / (e0 + nf) + e1 / (e1 + nf);
                }
            }
        red[tid] = ssum;
        __syncthreads();
        for (int st = 128; st > 0; st >>= 1) {
            if (tid < st) red[tid] += red[tid + st];
            __syncthreads();
        }
        if (tid == 0) atomicAdd(outsum, (double)red[0]);
    }
}

// Cluster scan (round-13 skeleton + per-tile GEMM flag polling): grid 32, cluster 16.
__global__ __launch_bounds__(256, 1) void lstm_scan_cluster(
    const float* __restrict__ Whh, const float* __restrict__ Agate,
    float* __restrict__ outbuf, __nv_bfloat16* __restrict__ xout,
    const int* __restrict__ cnt)
{
    __shared__ uint32_t sh_hp[2][256];
    __shared__ __align__(16) __nv_bfloat16 sh_wb[32];
    __shared__ __align__(8) uint64_t sh_bar;

    const int tid = threadIdx.x;
    const int w = tid >> 5, lane = tid & 31;
    const int half = lane >> 4, c16 = lane & 15;
    uint32_t rank;
    asm("mov.u32 %0, %%cluster_ctarank;" : "=r"(rank));
    const int dir = blockIdx.x >> 4;
    const bool fwd = (dir == 0);
    const float* Wd = Whh + (size_t)dir * G4 * DN;
    const float* Ad = Agate + (size_t)dir * L1N * G4;
    const int* cnt_d = cnt + dir * 16;

    const uint32_t bar_addr = smem_u32(&sh_bar);
    const uint32_t hp0 = smem_u32(&sh_hp[0][0]);
    const uint32_t hp1 = smem_u32(&sh_hp[1][0]);

    if (tid == 0)
        asm volatile("mbarrier.init.shared.b64 [%0], %1;" :: "r"(bar_addr), "r"(16u) : "memory");
    sh_hp[1][tid] = 0u;

    uint32_t wp[8][16];
    #pragma unroll
    for (int j = 0; j < 8; ++j) {
        int idx = 2 * j + half;
        int grow = (idx >> 2) * 512 + rank * 32 + 4 * w + (idx & 3);
        const float* src = Wd + (size_t)grow * DN + c16 * 32;
        #pragma unroll
        for (int q = 0; q < 8; ++q) {
            float4 v = *(const float4*)(src + q * 4);
            wp[j][2 * q]     = packbf(v.x, v.y);
            wp[j][2 * q + 1] = packbf(v.z, v.w);
        }
    }
    const int unit = 4 * w + 2 * c16 + half;      // valid for c16 < 2
    const int brow = rank * 32 + unit;
    __syncthreads();
    asm volatile("barrier.cluster.arrive.aligned;" ::: "memory");
    asm volatile("barrier.cluster.wait.aligned;" ::: "memory");

    float c_state = 0.f;
    uint32_t parity = 0;
    int last_mt = -1;

    for (int s = 0; s < L1N; ++s) {
        int t = fwd ? s : (L1N - 1 - s);

        float bias[4];
        if (c16 < 2) {
            int mt = t >> 6;
            if (mt != last_mt) {
                while (ld_acq_i(cnt_d + mt) < 32) {}
                last_mt = mt;
            }
            #pragma unroll
            for (int g = 0; g < 4; ++g)
                bias[g] = Ad[(size_t)t * G4 + g * 512 + brow];
        }

        if (s > 0) { bar_wait_cl(bar_addr, parity); parity ^= 1; }

        int rb = (s + 1) & 1;
        uint32_t hvp[16];
        #pragma unroll
        for (int q = 0; q < 4; ++q) {
            uint4 v = *(const uint4*)&sh_hp[rb][c16 * 16 + q * 4];
            hvp[4 * q + 0] = v.x; hvp[4 * q + 1] = v.y;
            hvp[4 * q + 2] = v.z; hvp[4 * q + 3] = v.w;
        }

        uint32_t pv[4];
        #pragma unroll
        for (int m = 0; m < 4; ++m) {
            __nv_bfloat162 accA = __float2bfloat162_rn(0.f), accB = accA;
            #pragma unroll
            for (int k = 0; k < 16; ++k) {
                accA = __hfma2(as_bf2(wp[2 * m][k]),     as_bf2(hvp[k]), accA);
                accB = __hfma2(as_bf2(wp[2 * m + 1][k]), as_bf2(hvp[k]), accB);
            }
            float sa = __low2float(accA) + __high2float(accA);
            float sb = __low2float(accB) + __high2float(accB);
            __nv_bfloat162 p = __float22bfloat162_rn(make_float2(sa, sb));
            #pragma unroll
            for (int off = 1; off < 16; off <<= 1) {
                uint32_t o = __shfl_xor_sync(0xffffffffu, as_u32(p), off);
                p = __hadd2(p, as_bf2(o));
            }
            pv[m] = as_u32(p);
        }

        if (c16 < 2) {
            float svg[4];
            #pragma unroll
            for (int g = 0; g < 4; ++g) {
                __nv_bfloat162 pg = as_bf2(pv[g]);
                svg[g] = (c16 == 0) ? __low2float(pg) : __high2float(pg);
            }
            float iv = sigm_t(svg[0] + bias[0]);
            float fv = sigm_t(svg[1] + bias[1]);
            float gv = tanh_t(svg[2] + bias[2]);
            float ov = sigm_t(svg[3] + bias[3]);
            c_state = fv * c_state + iv * gv;
            float h = ov * tanh_t(c_state);
            __nv_bfloat16 hb16 = __float2bfloat16(h);
            sh_wb[unit] = hb16;
            size_t off = (size_t)t * 1024 + dir * 512 + rank * 32 + unit;
            outbuf[off] = h;
            xout[off] = hb16;
        }
        __syncthreads();

        if (w == 0) {
            uint32_t base = ((s & 1) ? hp1 : hp0) + rank * 64;
            uint4 v0 = ((const uint4*)sh_wb)[2 * half];
            uint4 v1 = ((const uint4*)sh_wb)[2 * half + 1];
            st_peer_v4(base + (2 * half) * 16,     (uint32_t)c16, v0);
            st_peer_v4(base + (2 * half + 1) * 16, (uint32_t)c16, v1);
            __syncwarp();
            if (lane < 16) arrive_peer(bar_addr, (uint32_t)lane);
        }
    }
    asm volatile("barrier.cluster.arrive.aligned;" ::: "memory");
    asm volatile("barrier.cluster.wait.aligned;" ::: "memory");
}

__global__ void zkl_kernel(const float* __restrict__ eps, __nv_bfloat16* __restrict__ zb) {
    int i = blockIdx.x * 256 + threadIdx.x;
    float m = d_mu[i], pre = d_ps[i];
    float sg = log1pf(expf(pre));
    float zv = fmaf(eps[i], sg, m);
    d_z[i] = zv;
    zb[i] = __float2bfloat16(zv);
    float term = 0.5f * (sg * sg + m * m - 1.f) - logf(sg);
    __shared__ float red[256];
    red[threadIdx.x] = term;
    __syncthreads();
    for (int st = 128; st > 0; st >>= 1) {
        if (threadIdx.x < st) red[threadIdx.x] += red[threadIdx.x + st];
        __syncthreads();
    }
    if (threadIdx.x == 0) atomicAdd(d_kl, (double)red[0]);
}

__global__ void pos_kernel(const int* __restrict__ en, const float* __restrict__ E) {
    int t = blockIdx.x, tid = threadIdx.x;
    float4 a = *(const float4*)(d_z + t * DN + tid * 4);
    float4 b = *(const float4*)(E + (size_t)en[t] * DN + tid * 4);
    float s = a.x * b.x + a.y * b.y + a.z * b.z + a.w * b.w;
    #pragma unroll
    for (int off = 16; off > 0; off >>= 1) s += __shfl_xor_sync(0xffffffffu, s, off);
    __shared__ float red[4];
    if ((tid & 31) == 0) red[tid >> 5] = s;
    __syncthreads();
    if (tid == 0) d_pos[t] = expf(red[0] + red[1] + red[2] + red[3]);
}

__global__ void final_kernel(float* __restrict__ out) {
    int tid = threadIdx.x;
    float sx = 0.f;
    for (int t = tid; t < 1024; t += 256) {
        float pv = d_pos[t];
        sx += pv / (pv + d_neg[t]);
    }
    __shared__ float red[256];
    red[tid] = sx;
    __syncthreads();
    for (int st = 128; st > 0; st >>= 1) {
        if (tid < st) red[tid] += red[tid + st];
        __syncthreads();
    }
    if (tid == 0) {
        float sum_y = (float)(d_sumy[0] / 1024.0);
        out[0] = -(red[0] + sum_y - (float)d_kl[0]);
    }
}

extern "C" void kernel_launch(void* const* d_in, const int* in_sizes, int n_in,
                              void* d_out, int out_size)
{
    (void)in_sizes; (void)n_in; (void)out_size;
    const int*   en     = (const int*)d_in[0];
    const int*   fr     = (const int*)d_in[1];
    const int*   en_neg = (const int*)d_in[2];
    const int*   fr_neg = (const int*)d_in[3];
    const float* emb    = (const float*)d_in[4];
    const float* Wih[3] = {(const float*)d_in[5], (const float*)d_in[8], (const float*)d_in[11]};
    const float* Whh[3] = {(const float*)d_in[6], (const float*)d_in[9], (const float*)d_in[12]};
    const float* bb[3]  = {(const float*)d_in[7], (const float*)d_in[10], (const float*)d_in[13]};
    const float* Wmu1 = (const float*)d_in[14];
    const float* bmu1 = (const float*)d_in[15];
    const float* Wmu2 = (const float*)d_in[16];
    const float* bmu2 = (const float*)d_in[17];
    const float* Ws1  = (const float*)d_in[18];
    const float* bs1  = (const float*)d_in[19];
    const float* Ws2  = (const float*)d_in[20];
    const float* bs2  = (const float*)d_in[21];
    const float* E_en = (const float*)d_in[22];
    const float* E_fr = (const float*)d_in[23];
    const float* eps  = (const float*)d_in[24];

    float *buf0, *buf1, *Abuf, *mu, *ps, *z, *negp, *negfp;
    double *sumy;
    int *gc;
    __nv_bfloat16 *Wb, *X0, *X1, *Gen, *Gfrn, *Gfr, *zb, *hb, *t1b, *t2b, *Wm;
    cudaGetSymbolAddress((void**)&buf0, d_buf0);
    cudaGetSymbolAddress((void**)&buf1, d_buf1);
    cudaGetSymbolAddress((void**)&Abuf, d_A);
    cudaGetSymbolAddress((void**)&mu, d_mu);
    cudaGetSymbolAddress((void**)&ps, d_ps);
    cudaGetSymbolAddress((void**)&z, d_z);
    cudaGetSymbolAddress((void**)&negp, d_neg);
    cudaGetSymbolAddress((void**)&negfp, d_negf);
    cudaGetSymbolAddress((void**)&sumy, d_sumy);
    cudaGetSymbolAddress((void**)&gc, d_gcnt);
    cudaGetSymbolAddress((void**)&Wb, b_Wb);
    cudaGetSymbolAddress((void**)&X0, b_Xb);
    cudaGetSymbolAddress((void**)&X1, b_Xc);
    cudaGetSymbolAddress((void**)&Gen, b_Gen);
    cudaGetSymbolAddress((void**)&Gfrn, b_Gfrn);
    cudaGetSymbolAddress((void**)&Gfr, b_Gfr);
    cudaGetSymbolAddress((void**)&zb, b_zb);
    cudaGetSymbolAddress((void**)&hb, b_hb);
    cudaGetSymbolAddress((void**)&t1b, b_t1);
    cudaGetSymbolAddress((void**)&t2b, b_t2);
    cudaGetSymbolAddress((void**)&Wm, b_Wm);

    cudaFuncSetAttribute(lstm_scan_cluster,
                         cudaFuncAttributeNonPortableClusterSizeAllowed, 1);

    static cudaStream_t s2 = nullptr;
    static cudaEvent_t ev0 = nullptr, evA = nullptr, evB = nullptr, ev2 = nullptr;
    if (!s2) {
        cudaStreamCreateWithFlags(&s2, cudaStreamNonBlocking);
        cudaEventCreateWithFlags(&ev0, cudaEventDisableTiming);
        cudaEventCreateWithFlags(&evA, cudaEventDisableTiming);
        cudaEventCreateWithFlags(&evB, cudaEventDisableTiming);
        cudaEventCreateWithFlags(&ev2, cudaEventDisableTiming);
    }

    __nv_bfloat16* Xin[3]  = {X0, X1, X0};
    __nv_bfloat16* Xout[3] = {X1, X0, X1};
    float* outb[3] = {buf1, buf0, buf1};
    int    Kl[3]   = {512, 1024, 1024};

    // origin: reset + layer-0 input gather; fork s2
    reset_kernel<<<4, 256>>>();
    gatherb_kernel<<<1024, 128>>>(emb, en, X0);
    cudaEventRecord(ev0, 0);
    cudaStreamWaitEvent(s2, ev0, 0);

    auto launch_gemm_layer = [&](int l, cudaStream_t st) {
        for (int d = 0; d < 2; ++d) {
            gemm_bf16_kernel<<<dim3(32, 16), 256, 0, st>>>(
                Xin[l], Kl[l], Wb + (size_t)d * 2048 * Kl[l], Kl[l],
                bb[l] + d * 2048,
                Abuf + (size_t)d * 1024 * 2048, nullptr, 2048, Kl[l], 0,
                nullptr, nullptr, nullptr,
                d, gc + l * 32 + d * 16);
        }
    };
    auto launch_scan = [&](int l) {
        cudaLaunchConfig_t cfg = {};
        cfg.gridDim = dim3(32, 1, 1);
        cfg.blockDim = dim3(256, 1, 1);
        cfg.dynamicSmemBytes = 0;
        cfg.stream = 0;
        cudaLaunchAttribute at[1];
        at[0].id = cudaLaunchAttributeClusterDimension;
        at[0].val.clusterDim.x = 16;
        at[0].val.clusterDim.y = 1;
        at[0].val.clusterDim.z = 1;
        cfg.attrs = at;
        cfg.numAttrs = 1;
        cudaLaunchKernelEx(&cfg, lstm_scan_cluster, Whh[l], (const float*)Abuf,
                           outb[l], Xout[l], (const int*)(gc + l * 32));
    };

    // s2: layer-0 weight conv + GEMMs (flag-gated), then prep work during scan 0
    convb_kernel<<<2048, 256, 0, s2>>>(Wih[0], Wb, 2 * 2048 * 512 / 4);
    launch_gemm_layer(0, s2);
    gatherb_kernel<<<8192, 128, 0, s2>>>(E_en, en_neg, Gen);
    gatherb_kernel<<<8192, 128, 0, s2>>>(E_fr, fr_neg, Gfrn);
    gatherb_kernel<<<1024, 128, 0, s2>>>(E_fr, fr, Gfr);
    convb_kernel<<<256, 256, 0, s2>>>(Wmu1, Wm + 0 * 262144, 65536);
    convb_kernel<<<256, 256, 0, s2>>>(Wmu2, Wm + 1 * 262144, 65536);
    convb_kernel<<<256, 256, 0, s2>>>(Ws1,  Wm + 2 * 262144, 65536);
    convb_kernel<<<256, 256, 0, s2>>>(Ws2,  Wm + 3 * 262144, 65536);
    convb_kernel<<<4096, 256, 0, s2>>>(Wih[1], Wb, 2 * 2048 * 1024 / 4);

    // origin: scan 0 (polls layer-0 flags)
    launch_scan(0);
    cudaEventRecord(evA, 0);

    // s2: layer-1 GEMMs after scan 0 (reads Xout[0]); then layer-2 weight conv
    cudaStreamWaitEvent(s2, evA, 0);
    launch_gemm_layer(1, s2);
    launch_scan(1);                 // origin: scan 1 (polls layer-1 flags)
    cudaEventRecord(evB, 0);
    convb_kernel<<<4096, 256, 0, s2>>>(Wih[2], Wb, 2 * 2048 * 1024 / 4);
    cudaStreamWaitEvent(s2, evB, 0);
    launch_gemm_layer(2, s2);
    cudaEventRecord(ev2, s2);

    launch_scan(2);                 // origin: scan 2 (polls layer-2 flags)
    hsum_kernel<<<2048, 256>>>(hb);
    cudaStreamWaitEvent(0, ev2, 0); // join s2 (Wm conv + gathers + GEMMs done)

    gemm_bf16_kernel<<<dim3(8, 16), 256>>>(hb, 512, Wm + 0 * 262144, 512, bmu1,
        nullptr, t1b, 512, 512, 1, nullptr, nullptr, nullptr, 0, nullptr);
    gemm_bf16_kernel<<<dim3(8, 16), 256>>>(t1b, 512, Wm + 1 * 262144, 512, bmu2,
        mu, nullptr, 512, 512, 0, nullptr, nullptr, nullptr, 0, nullptr);
    gemm_bf16_kernel<<<dim3(8, 16), 256>>>(hb, 512, Wm + 2 * 262144, 512, bs1,
        nullptr, t2b, 512, 512, 1, nullptr, nullptr, nullptr, 0, nullptr);
    gemm_bf16_kernel<<<dim3(8, 16), 256>>>(t2b, 512, Wm + 3 * 262144, 512, bs2,
        ps, nullptr, 512, 512, 0, nullptr, nullptr, nullptr, 0, nullptr);

    zkl_kernel<<<2048, 256>>>(eps, zb);
    pos_kernel<<<1024, 128>>>(en, E_en);

    gemm_bf16_kernel<<<dim3(128, 16), 256>>>(zb, 512, Gen, 512, nullptr,
        nullptr, nullptr, 0, 512, 2, nullptr, negp, nullptr, 0, nullptr);
    gemm_bf16_kernel<<<dim3(128, 16), 256>>>(zb, 512, Gfrn, 512, nullptr,
        nullptr, nullptr, 0, 512, 2, nullptr, negfp, nullptr, 0, nullptr);
    gemm_bf16_kernel<<<dim3(16, 16), 256>>>(zb, 512, Gfr, 512, nullptr,
        nullptr, nullptr, 0, 512, 3, negfp, nullptr, sumy, 0, nullptr);

    final_kernel<<<1, 256>>>((float*)d_out);
}